// round 13
// baseline (speedup 1.0000x reference)
#include <cuda_runtime.h>
#include <math.h>

#define BB 64
#define SS 1024
#define UU 512
#define HH 512
#define DD 512
#define SPLIT 8
#define SCHUNK (SS / SPLIT)   // 128
#define ROWS_PER_BLK 64       // s-rows per scores block

// Scratch (no allocation allowed in kernel_launch)
__device__ float g_dec_attn[BB * UU];            // 128 KB
__device__ float g_cpart[SPLIT * BB * HH];       // 1 MB

// Accurate fast tanh: sign(x) * (1 - e)/(1 + e), e = exp(-2|x|).
// __expf is MUFU ex2-based (~2 ulp); overall error ~1e-6 rel.
__device__ __forceinline__ float fast_tanh(float x) {
    float ax = fabsf(x);
    float e  = __expf(-2.0f * ax);
    float r  = __fdividef(1.0f - e, 1.0f + e);
    return copysignf(r, x);
}

// ---------------------------------------------------------------------------
// K1: dec_attn[b,u] = dec_state[b,:] . W_dec[:,u] + b_dec[u]
// grid = B, block = 512 (one thread per u). W_dec column reads are coalesced
// across threads; whole W_dec (1 MB) is L2-resident after the first block.
// ---------------------------------------------------------------------------
__global__ void dec_proj_kernel(const float* __restrict__ dec_state,
                                const float* __restrict__ W_dec,
                                const float* __restrict__ b_dec) {
    const int b = blockIdx.x;
    const int u = threadIdx.x;
    __shared__ float sd[DD];
    sd[u] = dec_state[b * DD + u];
    __syncthreads();
    float acc = b_dec[u];
#pragma unroll 8
    for (int d = 0; d < DD; ++d)
        acc = fmaf(sd[d], W_dec[d * UU + u], acc);
    g_dec_attn[b * UU + u] = acc;
}

// ---------------------------------------------------------------------------
// K2: scores[b,s] = sum_u tanh(enc_attn[b,s,u] + cov[b,s]*W_cov[u] + dec_attn[b,u]) * w_attn[u]
// grid = (S/ROWS_PER_BLK, B), block = 256 (8 warps). One warp per s-row.
// Per-batch vectors cached in shared; enc_attn streamed via float4.
// Writes scores into the attn output region (softmax runs in place later).
// ---------------------------------------------------------------------------
__global__ void scores_kernel(const float* __restrict__ enc_attn,
                              const float* __restrict__ coverage,
                              const float* __restrict__ W_cov,
                              const float* __restrict__ w_attn,
                              float* __restrict__ scores) {
    const int b      = blockIdx.y;
    const int s_base = blockIdx.x * ROWS_PER_BLK;

    __shared__ float s_dec[UU];
    __shared__ float s_wc[UU];
    __shared__ float s_wa[UU];
    for (int i = threadIdx.x; i < UU; i += blockDim.x) {
        s_dec[i] = g_dec_attn[b * UU + i];
        s_wc[i]  = W_cov[i];
        s_wa[i]  = w_attn[i];
    }
    __syncthreads();

    const int warp = threadIdx.x >> 5;
    const int lane = threadIdx.x & 31;

    for (int r = warp; r < ROWS_PER_BLK; r += 8) {
        const int s  = s_base + r;
        const float cv = coverage[b * SS + s];
        const float4* ea =
            reinterpret_cast<const float4*>(enc_attn + ((size_t)(b * SS + s)) * UU);
        float sum = 0.0f;
#pragma unroll
        for (int it = 0; it < 4; ++it) {
            const int q = it * 32 + lane;   // float4 index, 128 per row
            const float4 e = ea[q];
            const int u = q * 4;
            sum += fast_tanh(fmaf(cv, s_wc[u + 0], e.x) + s_dec[u + 0]) * s_wa[u + 0];
            sum += fast_tanh(fmaf(cv, s_wc[u + 1], e.y) + s_dec[u + 1]) * s_wa[u + 1];
            sum += fast_tanh(fmaf(cv, s_wc[u + 2], e.z) + s_dec[u + 2]) * s_wa[u + 2];
            sum += fast_tanh(fmaf(cv, s_wc[u + 3], e.w) + s_dec[u + 3]) * s_wa[u + 3];
        }
#pragma unroll
        for (int o = 16; o; o >>= 1)
            sum += __shfl_xor_sync(0xffffffffu, sum, o);
        if (lane == 0)
            scores[b * SS + s] = sum;
    }
}

// ---------------------------------------------------------------------------
// K3: in-place softmax over S for each batch row. grid = B, block = S = 1024.
// ---------------------------------------------------------------------------
__global__ void softmax_kernel(float* __restrict__ attn) {
    const int b = blockIdx.x;
    const int t = threadIdx.x;
    __shared__ float red[32];
    __shared__ float bcast;

    float v = attn[b * SS + t];

    // max reduce
    float m = v;
#pragma unroll
    for (int o = 16; o; o >>= 1)
        m = fmaxf(m, __shfl_xor_sync(0xffffffffu, m, o));
    if ((t & 31) == 0) red[t >> 5] = m;
    __syncthreads();
    if (t < 32) {
        float x = red[t];
#pragma unroll
        for (int o = 16; o; o >>= 1)
            x = fmaxf(x, __shfl_xor_sync(0xffffffffu, x, o));
        if (t == 0) bcast = x;
    }
    __syncthreads();
    m = bcast;
    __syncthreads();

    // exp + sum reduce
    const float e = __expf(v - m);
    float s = e;
#pragma unroll
    for (int o = 16; o; o >>= 1)
        s += __shfl_xor_sync(0xffffffffu, s, o);
    if ((t & 31) == 0) red[t >> 5] = s;
    __syncthreads();
    if (t < 32) {
        float x = red[t];
#pragma unroll
        for (int o = 16; o; o >>= 1)
            x += __shfl_xor_sync(0xffffffffu, x, o);
        if (t == 0) bcast = x;
    }
    __syncthreads();

    attn[b * SS + t] = e * __frcp_rn(bcast);
}

// ---------------------------------------------------------------------------
// K4: partial c over an S-chunk: g_cpart[k,b,h] = sum_{s in chunk} attn[b,s]*enc[b,s,h]
// grid = (SPLIT, B), block = H = 512. Each iteration loads one contiguous
// 2 KB row of enc_output — fully coalesced. Deterministic (no atomics).
// ---------------------------------------------------------------------------
__global__ void cpart_kernel(const float* __restrict__ enc_output,
                             const float* __restrict__ attn) {
    const int b = blockIdx.y;
    const int k = blockIdx.x;
    const int h = threadIdx.x;

    __shared__ float sa[SCHUNK];
    if (h < SCHUNK) sa[h] = attn[b * SS + k * SCHUNK + h];
    __syncthreads();

    const float* base = enc_output + ((size_t)(b * SS + k * SCHUNK)) * HH + h;
    float acc = 0.0f;
#pragma unroll 8
    for (int i = 0; i < SCHUNK; ++i)
        acc = fmaf(sa[i], base[(size_t)i * HH], acc);

    g_cpart[(k * BB + b) * HH + h] = acc;
}

// ---------------------------------------------------------------------------
// K5: c[b,h] = sum_k g_cpart[k,b,h]
// ---------------------------------------------------------------------------
__global__ void creduce_kernel(float* __restrict__ c) {
    const int idx = blockIdx.x * blockDim.x + threadIdx.x;  // B*H = 32768
    float acc = 0.0f;
#pragma unroll
    for (int k = 0; k < SPLIT; ++k)
        acc += g_cpart[k * BB * HH + idx];
    c[idx] = acc;
}

extern "C" void kernel_launch(void* const* d_in, const int* in_sizes, int n_in,
                              void* d_out, int out_size) {
    const float* enc_output = (const float*)d_in[0];  // [B,S,H]
    const float* enc_attn   = (const float*)d_in[1];  // [B,S,U]
    const float* coverage   = (const float*)d_in[2];  // [B,S]
    const float* dec_state  = (const float*)d_in[3];  // [B,D]
    const float* W_dec      = (const float*)d_in[4];  // [D,U]
    const float* b_dec      = (const float*)d_in[5];  // [U]
    const float* W_cov      = (const float*)d_in[6];  // [1,U]
    const float* w_attn     = (const float*)d_in[7];  // [U,1]

    float* attn_out = (float*)d_out;        // [B,S,1] flattened, first B*S
    float* c_out    = attn_out + BB * SS;   // [B,H], next B*H

    dec_proj_kernel<<<BB, DD>>>(dec_state, W_dec, b_dec);
    scores_kernel<<<dim3(SS / ROWS_PER_BLK, BB), 256>>>(enc_attn, coverage,
                                                        W_cov, w_attn, attn_out);
    softmax_kernel<<<BB, SS>>>(attn_out);
    cpart_kernel<<<dim3(SPLIT, BB), HH>>>(enc_output, attn_out);
    creduce_kernel<<<(BB * HH) / 256, 256>>>(c_out);
}

// round 14
// speedup vs baseline: 1.0392x; 1.0392x over previous
#include <cuda_runtime.h>
#include <math.h>

#define BB 64
#define SS 1024
#define UU 512
#define HH 512
#define DD 512
#define SPLIT 16
#define SCHUNK (SS / SPLIT)   // 64
#define ROWS_PER_BLK 64       // s-rows per scores block

// Scratch (no allocation allowed in kernel_launch)
__device__ float g_dec_attn[BB * UU];            // 128 KB
__device__ float g_cpart[SPLIT * BB * HH];       // 2 MB

// Accurate fast tanh: sign(x) * (1 - e)/(1 + e), e = exp(-2|x|).
// 2 MUFU (EX2 + RCP) + a few ALU; ~1e-6 rel error.
__device__ __forceinline__ float fast_tanh(float x) {
    float ax = fabsf(x);
    float e  = __expf(-2.0f * ax);
    float r  = __fdividef(1.0f - e, 1.0f + e);
    return copysignf(r, x);
}

// ---------------------------------------------------------------------------
// K1: dec_attn[b,u] = dec_state[b,:] . W_dec[:,u] + b_dec[u]
// grid = (U/128, B) = 256 CTAs, 128 threads. W_dec is 1 MB -> L2-resident;
// each warp load of a W_dec row-slice is 512 B coalesced.
// ---------------------------------------------------------------------------
__global__ void dec_proj_kernel(const float* __restrict__ dec_state,
                                const float* __restrict__ W_dec,
                                const float* __restrict__ b_dec) {
    const int b = blockIdx.y;
    const int u = blockIdx.x * 128 + threadIdx.x;
    __shared__ float sd[DD];
#pragma unroll
    for (int i = 0; i < DD / 128; ++i)
        sd[threadIdx.x + i * 128] = dec_state[b * DD + threadIdx.x + i * 128];
    __syncthreads();
    float acc = b_dec[u];
#pragma unroll 8
    for (int d = 0; d < DD; ++d)
        acc = fmaf(sd[d], W_dec[d * UU + u], acc);
    g_dec_attn[b * UU + u] = acc;
}

// ---------------------------------------------------------------------------
// K2: scores[b,s] = sum_u tanh(enc_attn[b,s,u] + cov[b,s]*W_cov[u] + dec_attn[b,u]) * w_attn[u]
// grid = (S/64, B), block = 256 (8 warps). Each warp owns 8 consecutive rows
// and processes them two-at-a-time for 8 outstanding LDG.128 per thread.
// ---------------------------------------------------------------------------
__global__ void scores_kernel(const float* __restrict__ enc_attn,
                              const float* __restrict__ coverage,
                              const float* __restrict__ W_cov,
                              const float* __restrict__ w_attn,
                              float* __restrict__ scores) {
    const int b      = blockIdx.y;
    const int s_base = blockIdx.x * ROWS_PER_BLK;

    __shared__ float s_dec[UU];
    __shared__ float s_wc[UU];
    __shared__ float s_wa[UU];
    for (int i = threadIdx.x; i < UU; i += blockDim.x) {
        s_dec[i] = g_dec_attn[b * UU + i];
        s_wc[i]  = W_cov[i];
        s_wa[i]  = w_attn[i];
    }
    __syncthreads();

    const int warp = threadIdx.x >> 5;
    const int lane = threadIdx.x & 31;

    // warp handles rows [warp*8, warp*8+8), two rows per pass
    for (int r = warp * 8; r < warp * 8 + 8; r += 2) {
        const int s0 = s_base + r;
        const int s1 = s0 + 1;
        const float cv0 = coverage[b * SS + s0];
        const float cv1 = coverage[b * SS + s1];
        const float4* ea0 =
            reinterpret_cast<const float4*>(enc_attn + ((size_t)(b * SS + s0)) * UU);
        const float4* ea1 =
            reinterpret_cast<const float4*>(enc_attn + ((size_t)(b * SS + s1)) * UU);
        float sum0 = 0.0f, sum1 = 0.0f;
#pragma unroll
        for (int it = 0; it < 4; ++it) {
            const int q = it * 32 + lane;   // float4 index, 128 per row
            const float4 e0 = ea0[q];
            const float4 e1 = ea1[q];
            const int u = q * 4;
#pragma unroll
            for (int j = 0; j < 4; ++j) {
                const float ej0 = (j == 0) ? e0.x : (j == 1) ? e0.y : (j == 2) ? e0.z : e0.w;
                const float ej1 = (j == 0) ? e1.x : (j == 1) ? e1.y : (j == 2) ? e1.z : e1.w;
                const float de = s_dec[u + j];
                const float wc = s_wc[u + j];
                const float wa = s_wa[u + j];
                sum0 += fast_tanh(fmaf(cv0, wc, ej0) + de) * wa;
                sum1 += fast_tanh(fmaf(cv1, wc, ej1) + de) * wa;
            }
        }
#pragma unroll
        for (int o = 16; o; o >>= 1) {
            sum0 += __shfl_xor_sync(0xffffffffu, sum0, o);
            sum1 += __shfl_xor_sync(0xffffffffu, sum1, o);
        }
        if (lane == 0) {
            scores[b * SS + s0] = sum0;
            scores[b * SS + s1] = sum1;
        }
    }
}

// ---------------------------------------------------------------------------
// K3: in-place softmax over S for each batch row. grid = B, block = S = 1024.
// ---------------------------------------------------------------------------
__global__ void softmax_kernel(float* __restrict__ attn) {
    const int b = blockIdx.x;
    const int t = threadIdx.x;
    __shared__ float red[32];
    __shared__ float bcast;

    float v = attn[b * SS + t];

    float m = v;
#pragma unroll
    for (int o = 16; o; o >>= 1)
        m = fmaxf(m, __shfl_xor_sync(0xffffffffu, m, o));
    if ((t & 31) == 0) red[t >> 5] = m;
    __syncthreads();
    if (t < 32) {
        float x = red[t];
#pragma unroll
        for (int o = 16; o; o >>= 1)
            x = fmaxf(x, __shfl_xor_sync(0xffffffffu, x, o));
        if (t == 0) bcast = x;
    }
    __syncthreads();
    m = bcast;
    __syncthreads();

    const float e = __expf(v - m);
    float s = e;
#pragma unroll
    for (int o = 16; o; o >>= 1)
        s += __shfl_xor_sync(0xffffffffu, s, o);
    if ((t & 31) == 0) red[t >> 5] = s;
    __syncthreads();
    if (t < 32) {
        float x = red[t];
#pragma unroll
        for (int o = 16; o; o >>= 1)
            x += __shfl_xor_sync(0xffffffffu, x, o);
        if (t == 0) bcast = x;
    }
    __syncthreads();

    attn[b * SS + t] = e * __frcp_rn(bcast);
}

// ---------------------------------------------------------------------------
// K4: partial c over an S-chunk: g_cpart[k,b,:] = sum_{s in chunk} attn[b,s]*enc[b,s,:]
// grid = (SPLIT, B) = 1024 CTAs, 128 threads. Each thread owns 4 h-columns
// (float4); unroll 16 -> 16 outstanding LDG.128 per thread. Deterministic.
// ---------------------------------------------------------------------------
__global__ void cpart_kernel(const float* __restrict__ enc_output,
                             const float* __restrict__ attn) {
    const int b  = blockIdx.y;
    const int k  = blockIdx.x;
    const int h4 = threadIdx.x;          // float4 column index

    __shared__ float sa[SCHUNK];
    if (threadIdx.x < SCHUNK)
        sa[threadIdx.x] = attn[b * SS + k * SCHUNK + threadIdx.x];
    __syncthreads();

    const float4* base = reinterpret_cast<const float4*>(
        enc_output + ((size_t)(b * SS + k * SCHUNK)) * HH) + h4;

    float4 acc = make_float4(0.f, 0.f, 0.f, 0.f);
#pragma unroll 16
    for (int i = 0; i < SCHUNK; ++i) {
        const float4 e = base[(size_t)i * (HH / 4)];
        const float a = sa[i];
        acc.x = fmaf(a, e.x, acc.x);
        acc.y = fmaf(a, e.y, acc.y);
        acc.z = fmaf(a, e.z, acc.z);
        acc.w = fmaf(a, e.w, acc.w);
    }

    reinterpret_cast<float4*>(g_cpart + ((size_t)(k * BB + b)) * HH)[h4] = acc;
}

// ---------------------------------------------------------------------------
// K5: c[b,h] = sum_k g_cpart[k,b,h]
// ---------------------------------------------------------------------------
__global__ void creduce_kernel(float* __restrict__ c) {
    const int idx = blockIdx.x * blockDim.x + threadIdx.x;  // B*H = 32768
    float acc = 0.0f;
#pragma unroll
    for (int k = 0; k < SPLIT; ++k)
        acc += g_cpart[k * BB * HH + idx];
    c[idx] = acc;
}

extern "C" void kernel_launch(void* const* d_in, const int* in_sizes, int n_in,
                              void* d_out, int out_size) {
    const float* enc_output = (const float*)d_in[0];  // [B,S,H]
    const float* enc_attn   = (const float*)d_in[1];  // [B,S,U]
    const float* coverage   = (const float*)d_in[2];  // [B,S]
    const float* dec_state  = (const float*)d_in[3];  // [B,D]
    const float* W_dec      = (const float*)d_in[4];  // [D,U]
    const float* b_dec      = (const float*)d_in[5];  // [U]
    const float* W_cov      = (const float*)d_in[6];  // [1,U]
    const float* w_attn     = (const float*)d_in[7];  // [U,1]

    float* attn_out = (float*)d_out;        // [B,S,1] flattened, first B*S
    float* c_out    = attn_out + BB * SS;   // [B,H], next B*H

    dec_proj_kernel<<<dim3(UU / 128, BB), 128>>>(dec_state, W_dec, b_dec);
    scores_kernel<<<dim3(SS / ROWS_PER_BLK, BB), 256>>>(enc_attn, coverage,
                                                        W_cov, w_attn, attn_out);
    softmax_kernel<<<BB, SS>>>(attn_out);
    cpart_kernel<<<dim3(SPLIT, BB), 128>>>(enc_output, attn_out);
    creduce_kernel<<<(BB * HH) / 256, 256>>>(c_out);
}

// round 15
// speedup vs baseline: 1.2538x; 1.2066x over previous
#include <cuda_runtime.h>
#include <math.h>

#define BB 64
#define SS 1024
#define UU 512
#define HH 512
#define DD 512
#define SPLIT 16
#define SCHUNK (SS / SPLIT)   // 64
#define ROWS_PER_BLK 32       // s-rows per scores block (4 per warp)

// Scratch (no allocation allowed in kernel_launch)
__device__ float g_dec_attn[BB * UU];            // 128 KB
__device__ float g_cpart[SPLIT * BB * HH];       // 2 MB

// Exact-enough tanh without abs/copysign: (1-e)/(1+e), e = exp(-2x).
// Valid for all x; e overflows only for x < -44 -> clamp at -30 (tanh(-30)=-1
// to fp32 precision anyway). 1 FMNMX + 1 FMUL + MUFU.EX2 + 2 FADD + MUFU.RCP
// + FMUL. ~1e-6 rel error.
__device__ __forceinline__ float fast_tanh(float x) {
    float xm = fmaxf(x, -30.0f);
    float e  = __expf(-2.0f * xm);
    return __fdividef(1.0f - e, 1.0f + e);
}

// ---------------------------------------------------------------------------
// K1: dec_attn[b,u] = dec_state[b,:] . W_dec[:,u] + b_dec[u]
// grid = (U/128, B) = 256 CTAs, 128 threads. 4 independent accumulators break
// the dependent-FMA chain; W_dec (1 MB) is L2-resident.
// ---------------------------------------------------------------------------
__global__ void dec_proj_kernel(const float* __restrict__ dec_state,
                                const float* __restrict__ W_dec,
                                const float* __restrict__ b_dec) {
    const int b = blockIdx.y;
    const int u = blockIdx.x * 128 + threadIdx.x;
    __shared__ float sd[DD];
#pragma unroll
    for (int i = 0; i < DD / 128; ++i)
        sd[threadIdx.x + i * 128] = dec_state[b * DD + threadIdx.x + i * 128];
    __syncthreads();
    float a0 = b_dec[u], a1 = 0.f, a2 = 0.f, a3 = 0.f;
#pragma unroll 4
    for (int d = 0; d < DD; d += 4) {
        a0 = fmaf(sd[d + 0], W_dec[(d + 0) * UU + u], a0);
        a1 = fmaf(sd[d + 1], W_dec[(d + 1) * UU + u], a1);
        a2 = fmaf(sd[d + 2], W_dec[(d + 2) * UU + u], a2);
        a3 = fmaf(sd[d + 3], W_dec[(d + 3) * UU + u], a3);
    }
    g_dec_attn[b * UU + u] = (a0 + a1) + (a2 + a3);
}

// ---------------------------------------------------------------------------
// K2: scores[b,s] = sum_u tanh(enc_attn[b,s,u] + cov[b,s]*W_cov[u] + dec_attn[b,u]) * w_attn[u]
// grid = (S/32, B) = 2048 CTAs, block = 256 (8 warps). Each warp owns 4 rows,
// processed simultaneously: each unrolled iteration issues 4 independent
// LDG.128 per thread (16 per warp-pass), and keeps 4 independent FFMA
// accumulator chains. Per-batch vectors cached in shared.
// ---------------------------------------------------------------------------
__global__ void scores_kernel(const float* __restrict__ enc_attn,
                              const float* __restrict__ coverage,
                              const float* __restrict__ W_cov,
                              const float* __restrict__ w_attn,
                              float* __restrict__ scores) {
    const int b      = blockIdx.y;
    const int s_base = blockIdx.x * ROWS_PER_BLK;

    __shared__ float s_dec[UU];
    __shared__ float s_wc[UU];
    __shared__ float s_wa[UU];
    for (int i = threadIdx.x; i < UU; i += blockDim.x) {
        s_dec[i] = g_dec_attn[b * UU + i];
        s_wc[i]  = W_cov[i];
        s_wa[i]  = w_attn[i];
    }
    __syncthreads();

    const int warp = threadIdx.x >> 5;
    const int lane = threadIdx.x & 31;
    const int s0   = s_base + warp * 4;

    const float cv0 = coverage[b * SS + s0 + 0];
    const float cv1 = coverage[b * SS + s0 + 1];
    const float cv2 = coverage[b * SS + s0 + 2];
    const float cv3 = coverage[b * SS + s0 + 3];

    const float4* ea0 = reinterpret_cast<const float4*>(
        enc_attn + ((size_t)(b * SS + s0 + 0)) * UU);
    const float4* ea1 = reinterpret_cast<const float4*>(
        enc_attn + ((size_t)(b * SS + s0 + 1)) * UU);
    const float4* ea2 = reinterpret_cast<const float4*>(
        enc_attn + ((size_t)(b * SS + s0 + 2)) * UU);
    const float4* ea3 = reinterpret_cast<const float4*>(
        enc_attn + ((size_t)(b * SS + s0 + 3)) * UU);

    float sum0 = 0.f, sum1 = 0.f, sum2 = 0.f, sum3 = 0.f;

#pragma unroll
    for (int it = 0; it < 4; ++it) {
        const int q = it * 32 + lane;        // float4 index, 128 per row
        const float4 e0 = ea0[q];
        const float4 e1 = ea1[q];
        const float4 e2 = ea2[q];
        const float4 e3 = ea3[q];
        const int u = q * 4;
#pragma unroll
        for (int j = 0; j < 4; ++j) {
            const float ej0 = (j == 0) ? e0.x : (j == 1) ? e0.y : (j == 2) ? e0.z : e0.w;
            const float ej1 = (j == 0) ? e1.x : (j == 1) ? e1.y : (j == 2) ? e1.z : e1.w;
            const float ej2 = (j == 0) ? e2.x : (j == 1) ? e2.y : (j == 2) ? e2.z : e2.w;
            const float ej3 = (j == 0) ? e3.x : (j == 1) ? e3.y : (j == 2) ? e3.z : e3.w;
            const float de = s_dec[u + j];
            const float wc = s_wc[u + j];
            const float wa = s_wa[u + j];
            sum0 = fmaf(fast_tanh(fmaf(cv0, wc, ej0) + de), wa, sum0);
            sum1 = fmaf(fast_tanh(fmaf(cv1, wc, ej1) + de), wa, sum1);
            sum2 = fmaf(fast_tanh(fmaf(cv2, wc, ej2) + de), wa, sum2);
            sum3 = fmaf(fast_tanh(fmaf(cv3, wc, ej3) + de), wa, sum3);
        }
    }

#pragma unroll
    for (int o = 16; o; o >>= 1) {
        sum0 += __shfl_xor_sync(0xffffffffu, sum0, o);
        sum1 += __shfl_xor_sync(0xffffffffu, sum1, o);
        sum2 += __shfl_xor_sync(0xffffffffu, sum2, o);
        sum3 += __shfl_xor_sync(0xffffffffu, sum3, o);
    }
    if (lane == 0) {
        scores[b * SS + s0 + 0] = sum0;
        scores[b * SS + s0 + 1] = sum1;
        scores[b * SS + s0 + 2] = sum2;
        scores[b * SS + s0 + 3] = sum3;
    }
}

// ---------------------------------------------------------------------------
// K3: in-place softmax over S for each batch row. grid = B, block = S = 1024.
// ---------------------------------------------------------------------------
__global__ void softmax_kernel(float* __restrict__ attn) {
    const int b = blockIdx.x;
    const int t = threadIdx.x;
    __shared__ float red[32];
    __shared__ float bcast;

    float v = attn[b * SS + t];

    float m = v;
#pragma unroll
    for (int o = 16; o; o >>= 1)
        m = fmaxf(m, __shfl_xor_sync(0xffffffffu, m, o));
    if ((t & 31) == 0) red[t >> 5] = m;
    __syncthreads();
    if (t < 32) {
        float x = red[t];
#pragma unroll
        for (int o = 16; o; o >>= 1)
            x = fmaxf(x, __shfl_xor_sync(0xffffffffu, x, o));
        if (t == 0) bcast = x;
    }
    __syncthreads();
    m = bcast;
    __syncthreads();

    const float e = __expf(v - m);
    float s = e;
#pragma unroll
    for (int o = 16; o; o >>= 1)
        s += __shfl_xor_sync(0xffffffffu, s, o);
    if ((t & 31) == 0) red[t >> 5] = s;
    __syncthreads();
    if (t < 32) {
        float x = red[t];
#pragma unroll
        for (int o = 16; o; o >>= 1)
            x += __shfl_xor_sync(0xffffffffu, x, o);
        if (t == 0) bcast = x;
    }
    __syncthreads();

    attn[b * SS + t] = e * __frcp_rn(bcast);
}

// ---------------------------------------------------------------------------
// K4: partial c over an S-chunk: g_cpart[k,b,:] = sum_{s in chunk} attn[b,s]*enc[b,s,:]
// grid = (SPLIT, B) = 1024 CTAs, 128 threads. Each thread owns one float4
// h-column; unroll 16 -> 16 outstanding LDG.128. Each CTA streams 128 KB of
// contiguous enc_output. Deterministic (no atomics).
// ---------------------------------------------------------------------------
__global__ void cpart_kernel(const float* __restrict__ enc_output,
                             const float* __restrict__ attn) {
    const int b  = blockIdx.y;
    const int k  = blockIdx.x;
    const int h4 = threadIdx.x;          // float4 column index

    __shared__ float sa[SCHUNK];
    if (threadIdx.x < SCHUNK)
        sa[threadIdx.x] = attn[b * SS + k * SCHUNK + threadIdx.x];
    __syncthreads();

    const float4* base = reinterpret_cast<const float4*>(
        enc_output + ((size_t)(b * SS + k * SCHUNK)) * HH) + h4;

    float4 acc = make_float4(0.f, 0.f, 0.f, 0.f);
#pragma unroll 16
    for (int i = 0; i < SCHUNK; ++i) {
        const float4 e = base[(size_t)i * (HH / 4)];
        const float a = sa[i];
        acc.x = fmaf(a, e.x, acc.x);
        acc.y = fmaf(a, e.y, acc.y);
        acc.z = fmaf(a, e.z, acc.z);
        acc.w = fmaf(a, e.w, acc.w);
    }

    reinterpret_cast<float4*>(g_cpart + ((size_t)(k * BB + b)) * HH)[h4] = acc;
}

// ---------------------------------------------------------------------------
// K5: c[b,h] = sum_k g_cpart[k,b,h]
// ---------------------------------------------------------------------------
__global__ void creduce_kernel(float* __restrict__ c) {
    const int idx = blockIdx.x * blockDim.x + threadIdx.x;  // B*H = 32768
    float acc = 0.0f;
#pragma unroll
    for (int k = 0; k < SPLIT; ++k)
        acc += g_cpart[k * BB * HH + idx];
    c[idx] = acc;
}

extern "C" void kernel_launch(void* const* d_in, const int* in_sizes, int n_in,
                              void* d_out, int out_size) {
    const float* enc_output = (const float*)d_in[0];  // [B,S,H]
    const float* enc_attn   = (const float*)d_in[1];  // [B,S,U]
    const float* coverage   = (const float*)d_in[2];  // [B,S]
    const float* dec_state  = (const float*)d_in[3];  // [B,D]
    const float* W_dec      = (const float*)d_in[4];  // [D,U]
    const float* b_dec      = (const float*)d_in[5];  // [U]
    const float* W_cov      = (const float*)d_in[6];  // [1,U]
    const float* w_attn     = (const float*)d_in[7];  // [U,1]

    float* attn_out = (float*)d_out;        // [B,S,1] flattened, first B*S
    float* c_out    = attn_out + BB * SS;   // [B,H], next B*H

    dec_proj_kernel<<<dim3(UU / 128, BB), 128>>>(dec_state, W_dec, b_dec);
    scores_kernel<<<dim3(SS / ROWS_PER_BLK, BB), 256>>>(enc_attn, coverage,
                                                        W_cov, w_attn, attn_out);
    softmax_kernel<<<BB, SS>>>(attn_out);
    cpart_kernel<<<dim3(SPLIT, BB), 128>>>(enc_output, attn_out);
    creduce_kernel<<<(BB * HH) / 256, 256>>>(c_out);
}

// round 16
// speedup vs baseline: 1.2667x; 1.0102x over previous
#include <cuda_runtime.h>
#include <math.h>

#define BB 64
#define SS 1024
#define UU 512
#define HH 512
#define DD 512
#define SPLIT 16
#define SCHUNK (SS / SPLIT)   // 64
#define ROWS_PER_BLK 32       // s-rows per scores block (4 per warp)

// Scratch (no allocation allowed in kernel_launch)
__device__ float g_dec_attn[BB * UU];            // 128 KB
__device__ float g_cpart[SPLIT * BB * HH];       // 2 MB

// Exact-enough tanh without abs/copysign: (1-e)/(1+e), e = exp(-2x).
// Valid for all x; e overflows only for x < -44 -> clamp at -30 (tanh(-30)=-1
// to fp32 precision anyway). 1 FMNMX + 1 FMUL + MUFU.EX2 + 2 FADD + MUFU.RCP
// + FMUL. ~1e-6 rel error.
__device__ __forceinline__ float fast_tanh(float x) {
    float xm = fmaxf(x, -30.0f);
    float e  = __expf(-2.0f * xm);
    return __fdividef(1.0f - e, 1.0f + e);
}

// ---------------------------------------------------------------------------
// K1: dec_attn[b,u] = dec_state[b,:] . W_dec[:,u] + b_dec[u]
// grid = (U/128, B) = 256 CTAs, 128 threads. 4 independent accumulators break
// the dependent-FMA chain; W_dec (1 MB) is L2-resident.
// ---------------------------------------------------------------------------
__global__ void dec_proj_kernel(const float* __restrict__ dec_state,
                                const float* __restrict__ W_dec,
                                const float* __restrict__ b_dec) {
    const int b = blockIdx.y;
    const int u = blockIdx.x * 128 + threadIdx.x;
    __shared__ float sd[DD];
#pragma unroll
    for (int i = 0; i < DD / 128; ++i)
        sd[threadIdx.x + i * 128] = dec_state[b * DD + threadIdx.x + i * 128];
    __syncthreads();
    float a0 = b_dec[u], a1 = 0.f, a2 = 0.f, a3 = 0.f;
#pragma unroll 4
    for (int d = 0; d < DD; d += 4) {
        a0 = fmaf(sd[d + 0], W_dec[(d + 0) * UU + u], a0);
        a1 = fmaf(sd[d + 1], W_dec[(d + 1) * UU + u], a1);
        a2 = fmaf(sd[d + 2], W_dec[(d + 2) * UU + u], a2);
        a3 = fmaf(sd[d + 3], W_dec[(d + 3) * UU + u], a3);
    }
    g_dec_attn[b * UU + u] = (a0 + a1) + (a2 + a3);
}

// ---------------------------------------------------------------------------
// K2: scores[b,s] = sum_u tanh(enc_attn[b,s,u] + cov[b,s]*W_cov[u] + dec_attn[b,u]) * w_attn[u]
// grid = (S/32, B) = 2048 CTAs, block = 256 (8 warps). Each warp owns 4 rows,
// processed simultaneously: each unrolled iteration issues 4 independent
// LDG.128 per thread (16 per warp-pass), and keeps 4 independent FFMA
// accumulator chains. Per-batch vectors cached in shared.
// ---------------------------------------------------------------------------
__global__ void scores_kernel(const float* __restrict__ enc_attn,
                              const float* __restrict__ coverage,
                              const float* __restrict__ W_cov,
                              const float* __restrict__ w_attn,
                              float* __restrict__ scores) {
    const int b      = blockIdx.y;
    const int s_base = blockIdx.x * ROWS_PER_BLK;

    __shared__ float s_dec[UU];
    __shared__ float s_wc[UU];
    __shared__ float s_wa[UU];
    for (int i = threadIdx.x; i < UU; i += blockDim.x) {
        s_dec[i] = g_dec_attn[b * UU + i];
        s_wc[i]  = W_cov[i];
        s_wa[i]  = w_attn[i];
    }
    __syncthreads();

    const int warp = threadIdx.x >> 5;
    const int lane = threadIdx.x & 31;
    const int s0   = s_base + warp * 4;

    const float cv0 = coverage[b * SS + s0 + 0];
    const float cv1 = coverage[b * SS + s0 + 1];
    const float cv2 = coverage[b * SS + s0 + 2];
    const float cv3 = coverage[b * SS + s0 + 3];

    const float4* ea0 = reinterpret_cast<const float4*>(
        enc_attn + ((size_t)(b * SS + s0 + 0)) * UU);
    const float4* ea1 = reinterpret_cast<const float4*>(
        enc_attn + ((size_t)(b * SS + s0 + 1)) * UU);
    const float4* ea2 = reinterpret_cast<const float4*>(
        enc_attn + ((size_t)(b * SS + s0 + 2)) * UU);
    const float4* ea3 = reinterpret_cast<const float4*>(
        enc_attn + ((size_t)(b * SS + s0 + 3)) * UU);

    float sum0 = 0.f, sum1 = 0.f, sum2 = 0.f, sum3 = 0.f;

#pragma unroll
    for (int it = 0; it < 4; ++it) {
        const int q = it * 32 + lane;        // float4 index, 128 per row
        const float4 e0 = ea0[q];
        const float4 e1 = ea1[q];
        const float4 e2 = ea2[q];
        const float4 e3 = ea3[q];
        const int u = q * 4;
#pragma unroll
        for (int j = 0; j < 4; ++j) {
            const float ej0 = (j == 0) ? e0.x : (j == 1) ? e0.y : (j == 2) ? e0.z : e0.w;
            const float ej1 = (j == 0) ? e1.x : (j == 1) ? e1.y : (j == 2) ? e1.z : e1.w;
            const float ej2 = (j == 0) ? e2.x : (j == 1) ? e2.y : (j == 2) ? e2.z : e2.w;
            const float ej3 = (j == 0) ? e3.x : (j == 1) ? e3.y : (j == 2) ? e3.z : e3.w;
            const float de = s_dec[u + j];
            const float wc = s_wc[u + j];
            const float wa = s_wa[u + j];
            sum0 = fmaf(fast_tanh(fmaf(cv0, wc, ej0) + de), wa, sum0);
            sum1 = fmaf(fast_tanh(fmaf(cv1, wc, ej1) + de), wa, sum1);
            sum2 = fmaf(fast_tanh(fmaf(cv2, wc, ej2) + de), wa, sum2);
            sum3 = fmaf(fast_tanh(fmaf(cv3, wc, ej3) + de), wa, sum3);
        }
    }

#pragma unroll
    for (int o = 16; o; o >>= 1) {
        sum0 += __shfl_xor_sync(0xffffffffu, sum0, o);
        sum1 += __shfl_xor_sync(0xffffffffu, sum1, o);
        sum2 += __shfl_xor_sync(0xffffffffu, sum2, o);
        sum3 += __shfl_xor_sync(0xffffffffu, sum3, o);
    }
    if (lane == 0) {
        scores[b * SS + s0 + 0] = sum0;
        scores[b * SS + s0 + 1] = sum1;
        scores[b * SS + s0 + 2] = sum2;
        scores[b * SS + s0 + 3] = sum3;
    }
}

// ---------------------------------------------------------------------------
// K3: in-place softmax over S for each batch row. grid = B, block = S = 1024.
// ---------------------------------------------------------------------------
__global__ void softmax_kernel(float* __restrict__ attn) {
    const int b = blockIdx.x;
    const int t = threadIdx.x;
    __shared__ float red[32];
    __shared__ float bcast;

    float v = attn[b * SS + t];

    float m = v;
#pragma unroll
    for (int o = 16; o; o >>= 1)
        m = fmaxf(m, __shfl_xor_sync(0xffffffffu, m, o));
    if ((t & 31) == 0) red[t >> 5] = m;
    __syncthreads();
    if (t < 32) {
        float x = red[t];
#pragma unroll
        for (int o = 16; o; o >>= 1)
            x = fmaxf(x, __shfl_xor_sync(0xffffffffu, x, o));
        if (t == 0) bcast = x;
    }
    __syncthreads();
    m = bcast;
    __syncthreads();

    const float e = __expf(v - m);
    float s = e;
#pragma unroll
    for (int o = 16; o; o >>= 1)
        s += __shfl_xor_sync(0xffffffffu, s, o);
    if ((t & 31) == 0) red[t >> 5] = s;
    __syncthreads();
    if (t < 32) {
        float x = red[t];
#pragma unroll
        for (int o = 16; o; o >>= 1)
            x += __shfl_xor_sync(0xffffffffu, x, o);
        if (t == 0) bcast = x;
    }
    __syncthreads();

    attn[b * SS + t] = e * __frcp_rn(bcast);
}

// ---------------------------------------------------------------------------
// K4: partial c over an S-chunk: g_cpart[k,b,:] = sum_{s in chunk} attn[b,s]*enc[b,s,:]
// grid = (SPLIT, B) = 1024 CTAs, 128 threads. Each thread owns one float4
// h-column; unroll 16 -> 16 outstanding LDG.128. Each CTA streams 128 KB of
// contiguous enc_output. Deterministic (no atomics).
// ---------------------------------------------------------------------------
__global__ void cpart_kernel(const float* __restrict__ enc_output,
                             const float* __restrict__ attn) {
    const int b  = blockIdx.y;
    const int k  = blockIdx.x;
    const int h4 = threadIdx.x;          // float4 column index

    __shared__ float sa[SCHUNK];
    if (threadIdx.x < SCHUNK)
        sa[threadIdx.x] = attn[b * SS + k * SCHUNK + threadIdx.x];
    __syncthreads();

    const float4* base = reinterpret_cast<const float4*>(
        enc_output + ((size_t)(b * SS + k * SCHUNK)) * HH) + h4;

    float4 acc = make_float4(0.f, 0.f, 0.f, 0.f);
#pragma unroll 16
    for (int i = 0; i < SCHUNK; ++i) {
        const float4 e = base[(size_t)i * (HH / 4)];
        const float a = sa[i];
        acc.x = fmaf(a, e.x, acc.x);
        acc.y = fmaf(a, e.y, acc.y);
        acc.z = fmaf(a, e.z, acc.z);
        acc.w = fmaf(a, e.w, acc.w);
    }

    reinterpret_cast<float4*>(g_cpart + ((size_t)(k * BB + b)) * HH)[h4] = acc;
}

// ---------------------------------------------------------------------------
// K5: c[b,h] = sum_k g_cpart[k,b,h]
// ---------------------------------------------------------------------------
__global__ void creduce_kernel(float* __restrict__ c) {
    const int idx = blockIdx.x * blockDim.x + threadIdx.x;  // B*H = 32768
    float acc = 0.0f;
#pragma unroll
    for (int k = 0; k < SPLIT; ++k)
        acc += g_cpart[k * BB * HH + idx];
    c[idx] = acc;
}

extern "C" void kernel_launch(void* const* d_in, const int* in_sizes, int n_in,
                              void* d_out, int out_size) {
    const float* enc_output = (const float*)d_in[0];  // [B,S,H]
    const float* enc_attn   = (const float*)d_in[1];  // [B,S,U]
    const float* coverage   = (const float*)d_in[2];  // [B,S]
    const float* dec_state  = (const float*)d_in[3];  // [B,D]
    const float* W_dec      = (const float*)d_in[4];  // [D,U]
    const float* b_dec      = (const float*)d_in[5];  // [U]
    const float* W_cov      = (const float*)d_in[6];  // [1,U]
    const float* w_attn     = (const float*)d_in[7];  // [U,1]

    float* attn_out = (float*)d_out;        // [B,S,1] flattened, first B*S
    float* c_out    = attn_out + BB * SS;   // [B,H], next B*H

    dec_proj_kernel<<<dim3(UU / 128, BB), 128>>>(dec_state, W_dec, b_dec);
    scores_kernel<<<dim3(SS / ROWS_PER_BLK, BB), 256>>>(enc_attn, coverage,
                                                        W_cov, w_attn, attn_out);
    softmax_kernel<<<BB, SS>>>(attn_out);
    cpart_kernel<<<dim3(SPLIT, BB), 128>>>(enc_output, attn_out);
    creduce_kernel<<<(BB * HH) / 256, 256>>>(c_out);
}